// round 6
// baseline (speedup 1.0000x reference)
#include <cuda_runtime.h>
#include <cuda_bf16.h>
#include <math.h>

#define NN 50000
#define EE 800000
#define DD 128
#define KK 64
#define BN_EPS_F 1e-5f

// ---------------- scratch (static device memory) ----------------
__device__ float    g_agg[NN * DD];
__device__ float    g_h[NN * DD];
__device__ float    g_z[NN * DD];
__device__ double   g_stats[4 * DD];
__device__ float    g_scale[DD];
__device__ float    g_shift[DD];
__device__ unsigned g_wf[16 * 8192];   // [mat 0..3][half hi/lo][8192] bf16-pair fragments
// CSR scratch
__device__ int      g_deg[NN];
__device__ int      g_off[NN + 1];
__device__ int      g_cursor[NN];
__device__ int      g_csr[EE];

// ---------------- bf16 helpers ----------------
__device__ __forceinline__ unsigned short bfbits(float x) {
    __nv_bfloat16 h = __float2bfloat16(x);
    return *reinterpret_cast<unsigned short*>(&h);
}
__device__ __forceinline__ float bf2f(unsigned short u) {
    __nv_bfloat16 h = *reinterpret_cast<__nv_bfloat16*>(&u);
    return __bfloat162float(h);
}
__device__ __forceinline__ void mma_bf16(float d[4], const unsigned a[4], unsigned b0, unsigned b1) {
    asm volatile("mma.sync.aligned.m16n8k16.row.col.f32.bf16.bf16.f32 "
        "{%0,%1,%2,%3}, {%4,%5,%6,%7}, {%8,%9}, {%0,%1,%2,%3};"
        : "+f"(d[0]), "+f"(d[1]), "+f"(d[2]), "+f"(d[3])
        : "r"(a[0]), "r"(a[1]), "r"(a[2]), "r"(a[3]), "r"(b0), "r"(b1));
}

// ---------------- weight prep: split-bf16 fragment layout ----------------
// m16n8k16 B-frag: b0 = {W[k0][n], W[k0+1][n]} with k0 = ks*16+2t, b1: k0+8.
// index = (ks*16+nt)*64 + lane*2 + j  (ks 0..7, nt 0..15, lane 0..31, j 0..1)
__global__ void k_prepw(const float* __restrict__ W1a, const float* __restrict__ W1b,
                        const float* __restrict__ W2a, const float* __restrict__ W2b) {
    const float* Ws[4] = {W1a, W1b, W2a, W2b};
    const float* W = Ws[blockIdx.x];
    unsigned* hi = g_wf + (blockIdx.x * 2 + 0) * 8192;
    unsigned* lo = g_wf + (blockIdx.x * 2 + 1) * 8192;
    for (int f = threadIdx.x; f < 8192; f += blockDim.x) {
        int j    = f & 1;
        int lane = (f >> 1) & 31;
        int nt   = (f >> 6) & 15;
        int ks   = f >> 10;
        int t = lane & 3, g = lane >> 2;
        int k0 = ks * 16 + 2 * t + j * 8;
        int n  = nt * 8 + g;
        float w0 = W[k0 * DD + n], w1 = W[(k0 + 1) * DD + n];
        unsigned short h0 = bfbits(w0), h1 = bfbits(w1);
        hi[f] = (unsigned)h0 | ((unsigned)h1 << 16);
        lo[f] = (unsigned)bfbits(w0 - bf2f(h0)) | ((unsigned)bfbits(w1 - bf2f(h1)) << 16);
    }
}

// ---------------- zero degree + stats ----------------
__global__ void k_zero() {
    int i = blockIdx.x * blockDim.x + threadIdx.x;
    if (i < NN) g_deg[i] = 0;
    if (i < 512) g_stats[i] = 0.0;
}

// ---------------- in-degree histogram ----------------
__global__ void k_hist(const int* __restrict__ ei) {
    int e = blockIdx.x * blockDim.x + threadIdx.x;
    if (e >= EE) return;
    int d = __ldg(ei + EE + e);
    if ((unsigned)d < NN) atomicAdd(&g_deg[d], 1);
}

// ---------------- single-block exclusive scan ----------------
__global__ void __launch_bounds__(1024) k_scan() {
    __shared__ int swarp[32];
    int tid = threadIdx.x;
    int lane = tid & 31, w = tid >> 5;
    int running = 0;
    for (int base = 0; base < NN; base += 1024) {
        int i = base + tid;
        int v = (i < NN) ? g_deg[i] : 0;
        int xv = v;
        #pragma unroll
        for (int o = 1; o < 32; o <<= 1) {
            int y = __shfl_up_sync(0xffffffffu, xv, o);
            if (lane >= o) xv += y;
        }
        if (lane == 31) swarp[w] = xv;
        __syncthreads();
        if (w == 0) {
            int y = swarp[lane];
            #pragma unroll
            for (int o = 1; o < 32; o <<= 1) {
                int z = __shfl_up_sync(0xffffffffu, y, o);
                if (lane >= o) y += z;
            }
            swarp[lane] = y;
        }
        __syncthreads();
        int excl = xv - v + (w > 0 ? swarp[w - 1] : 0) + running;
        if (i < NN) { g_off[i] = excl; g_cursor[i] = excl; }
        int chunk_total = swarp[31];
        __syncthreads();
        running += chunk_total;
    }
    if (tid == 0) g_off[NN] = running;
}

// ---------------- permute: fill CSR src lists ----------------
__global__ void k_permute(const int* __restrict__ ei) {
    int e = blockIdx.x * blockDim.x + threadIdx.x;
    if (e >= EE) return;
    int s = __ldg(ei + e);
    int d = __ldg(ei + EE + e);
    if ((unsigned)s >= NN || (unsigned)d >= NN) return;
    int pos = atomicAdd(&g_cursor[d], 1);
    g_csr[pos] = s;
}

// ---------------- gather: agg[n] = (1+eps)*feat[n] + sum_{s in N(n)} feat[s] ----------------
__global__ void k_gather(const float* __restrict__ feat, const float* __restrict__ epsp) {
    int gw = (blockIdx.x * blockDim.x + threadIdx.x) >> 5;
    int lane = threadIdx.x & 31;
    if (gw >= NN) return;
    float e = 1.0f + *epsp;
    float4 acc = __ldg((const float4*)(feat + (size_t)gw * DD) + lane);
    acc.x *= e; acc.y *= e; acc.z *= e; acc.w *= e;
    int beg = __ldg(&g_off[gw]);
    int end = __ldg(&g_off[gw + 1]);
    int j = beg;
    for (; j + 4 <= end; j += 4) {
        int s0 = __ldg(&g_csr[j]);
        int s1 = __ldg(&g_csr[j + 1]);
        int s2 = __ldg(&g_csr[j + 2]);
        int s3 = __ldg(&g_csr[j + 3]);
        float4 v0 = __ldg((const float4*)(feat + (size_t)s0 * DD) + lane);
        float4 v1 = __ldg((const float4*)(feat + (size_t)s1 * DD) + lane);
        float4 v2 = __ldg((const float4*)(feat + (size_t)s2 * DD) + lane);
        float4 v3 = __ldg((const float4*)(feat + (size_t)s3 * DD) + lane);
        acc.x += (v0.x + v1.x) + (v2.x + v3.x);
        acc.y += (v0.y + v1.y) + (v2.y + v3.y);
        acc.z += (v0.z + v1.z) + (v2.z + v3.z);
        acc.w += (v0.w + v1.w) + (v2.w + v3.w);
    }
    for (; j < end; j++) {
        int s = __ldg(&g_csr[j]);
        float4 v = __ldg((const float4*)(feat + (size_t)s * DD) + lane);
        acc.x += v.x; acc.y += v.y; acc.z += v.z; acc.w += v.w;
    }
    ((float4*)(g_agg + (size_t)gw * DD))[lane] = acc;
}

// ---------------- split-bf16 tensor-core fused 2-GEMM MLP + BN stats ----------------
// 256 threads (8 warps). Tile = 64 rows. warp: band=warp>>2? -> band = warp>>1 (16 rows),
// nhalf = warp&1 (cols nhalf*64, 8 n-tiles of 8).
// smem u32 layout:
//   sWahi 0 | sWalo 8192 | sWbhi 16384 | sWblo 24576
//   sAhi 32768 (64x68) | sAlo 37120 | sThi 41472 | sTlo 45824 | sS(float) 50176 (256)
// total 50432 u32 = 201728 B
__global__ void __launch_bounds__(256, 1) k_mlp3(
    const float* __restrict__ ba, const float* __restrict__ bb, int layer)
{
    extern __shared__ unsigned smu[];
    unsigned* sWahi = smu;
    unsigned* sWalo = smu + 8192;
    unsigned* sWbhi = smu + 16384;
    unsigned* sWblo = smu + 24576;
    unsigned* sAhi  = smu + 32768;
    unsigned* sAlo  = smu + 37120;
    unsigned* sThi  = smu + 41472;
    unsigned* sTlo  = smu + 45824;
    float*    sS    = (float*)(smu + 50176);

    int tid = threadIdx.x;
    const unsigned* wsrc = g_wf + (size_t)layer * 2 * 16384;  // Wa(hi,lo), Wb(hi,lo) contiguous
    for (int i = tid; i < 8192; i += 256)                      // 32768 u32 as uint4
        ((uint4*)sWahi)[i] = ((const uint4*)wsrc)[i];
    sS[tid] = 0.0f;

    int warp = tid >> 5, lane = tid & 31;
    int band = warp >> 1, nhalf = warp & 1;
    int g = lane >> 2, t = lane & 3;
    int band16 = band * 16;
    int arow = (band16 + g) * 68;

    float bav[8][2], bbv[8][2];
    #pragma unroll
    for (int nt = 0; nt < 8; nt++) {
        int c = (nhalf * 8 + nt) * 8 + 2 * t;
        bav[nt][0] = ba[c]; bav[nt][1] = ba[c + 1];
        bbv[nt][0] = bb[c]; bbv[nt][1] = bb[c + 1];
    }

    float ssum[16], ssq[16];
    #pragma unroll
    for (int k = 0; k < 16; k++) { ssum[k] = 0.f; ssq[k] = 0.f; }
    __syncthreads();

    const int ntiles = (NN + 63) / 64;
    for (int tno = blockIdx.x; tno < ntiles; tno += 148) {
        int row0 = tno * 64;

        // ---- stage A tile: split fp32 -> bf16 hi/lo packed pairs ----
        for (int i = tid; i < 2048; i += 256) {
            int r = i >> 5, c4 = i & 31;
            float4 v = make_float4(0.f, 0.f, 0.f, 0.f);
            if (row0 + r < NN)
                v = ((const float4*)(g_agg + (size_t)(row0 + r) * DD))[c4];
            unsigned short h0 = bfbits(v.x), h1 = bfbits(v.y), h2 = bfbits(v.z), h3 = bfbits(v.w);
            int base = r * 68 + c4 * 2;
            sAhi[base]     = (unsigned)h0 | ((unsigned)h1 << 16);
            sAhi[base + 1] = (unsigned)h2 | ((unsigned)h3 << 16);
            sAlo[base]     = (unsigned)bfbits(v.x - bf2f(h0)) | ((unsigned)bfbits(v.y - bf2f(h1)) << 16);
            sAlo[base + 1] = (unsigned)bfbits(v.z - bf2f(h2)) | ((unsigned)bfbits(v.w - bf2f(h3)) << 16);
        }
        __syncthreads();

        // ---- GEMM1: T = relu(A @ Wa + ba) ----
        float acc[8][4];
        #pragma unroll
        for (int nt = 0; nt < 8; nt++) {
            acc[nt][0] = bav[nt][0]; acc[nt][1] = bav[nt][1];
            acc[nt][2] = bav[nt][0]; acc[nt][3] = bav[nt][1];
        }
        #pragma unroll
        for (int ks = 0; ks < 8; ks++) {
            unsigned ah[4], al[4];
            int w0 = ks * 8 + t;
            ah[0] = sAhi[arow + w0];       ah[1] = sAhi[arow + 544 + w0];
            ah[2] = sAhi[arow + w0 + 4];   ah[3] = sAhi[arow + 544 + w0 + 4];
            al[0] = sAlo[arow + w0];       al[1] = sAlo[arow + 544 + w0];
            al[2] = sAlo[arow + w0 + 4];   al[3] = sAlo[arow + 544 + w0 + 4];
            #pragma unroll
            for (int nt = 0; nt < 8; nt++) {
                int fb = (ks * 16 + nhalf * 8 + nt) * 64 + lane * 2;
                uint2 bh = *(const uint2*)(sWahi + fb);
                uint2 bl = *(const uint2*)(sWalo + fb);
                mma_bf16(acc[nt], ah, bh.x, bh.y);
                mma_bf16(acc[nt], ah, bl.x, bl.y);
                mma_bf16(acc[nt], al, bh.x, bh.y);
            }
        }
        // relu + split -> sT
        #pragma unroll
        for (int nt = 0; nt < 8; nt++) {
            float m0 = fmaxf(acc[nt][0], 0.f), m1 = fmaxf(acc[nt][1], 0.f);
            float m2 = fmaxf(acc[nt][2], 0.f), m3 = fmaxf(acc[nt][3], 0.f);
            int wd = (nhalf * 8 + nt) * 4 + t;
            unsigned short h0 = bfbits(m0), h1 = bfbits(m1), h2 = bfbits(m2), h3 = bfbits(m3);
            sThi[arow + wd]       = (unsigned)h0 | ((unsigned)h1 << 16);
            sTlo[arow + wd]       = (unsigned)bfbits(m0 - bf2f(h0)) | ((unsigned)bfbits(m1 - bf2f(h1)) << 16);
            sThi[arow + 544 + wd] = (unsigned)h2 | ((unsigned)h3 << 16);
            sTlo[arow + 544 + wd] = (unsigned)bfbits(m2 - bf2f(h2)) | ((unsigned)bfbits(m3 - bf2f(h3)) << 16);
        }
        __syncthreads();

        // ---- GEMM2: h = T @ Wb + bb ----
        #pragma unroll
        for (int nt = 0; nt < 8; nt++) {
            acc[nt][0] = bbv[nt][0]; acc[nt][1] = bbv[nt][1];
            acc[nt][2] = bbv[nt][0]; acc[nt][3] = bbv[nt][1];
        }
        #pragma unroll
        for (int ks = 0; ks < 8; ks++) {
            unsigned ah[4], al[4];
            int w0 = ks * 8 + t;
            ah[0] = sThi[arow + w0];       ah[1] = sThi[arow + 544 + w0];
            ah[2] = sThi[arow + w0 + 4];   ah[3] = sThi[arow + 544 + w0 + 4];
            al[0] = sTlo[arow + w0];       al[1] = sTlo[arow + 544 + w0];
            al[2] = sTlo[arow + w0 + 4];   al[3] = sTlo[arow + 544 + w0 + 4];
            #pragma unroll
            for (int nt = 0; nt < 8; nt++) {
                int fb = (ks * 16 + nhalf * 8 + nt) * 64 + lane * 2;
                uint2 bh = *(const uint2*)(sWbhi + fb);
                uint2 bl = *(const uint2*)(sWblo + fb);
                mma_bf16(acc[nt], ah, bh.x, bh.y);
                mma_bf16(acc[nt], ah, bl.x, bl.y);
                mma_bf16(acc[nt], al, bh.x, bh.y);
            }
        }

        // ---- store h + accumulate BN stats (valid rows only) ----
        int ra = row0 + band16 + g;
        int rb = ra + 8;
        bool va = ra < NN, vb = rb < NN;
        #pragma unroll
        for (int nt = 0; nt < 8; nt++) {
            int c = (nhalf * 8 + nt) * 8 + 2 * t;
            if (va) {
                *(float2*)(g_h + (size_t)ra * DD + c) = make_float2(acc[nt][0], acc[nt][1]);
                ssum[nt * 2]     += acc[nt][0]; ssq[nt * 2]     += acc[nt][0] * acc[nt][0];
                ssum[nt * 2 + 1] += acc[nt][1]; ssq[nt * 2 + 1] += acc[nt][1] * acc[nt][1];
            }
            if (vb) {
                *(float2*)(g_h + (size_t)rb * DD + c) = make_float2(acc[nt][2], acc[nt][3]);
                ssum[nt * 2]     += acc[nt][2]; ssq[nt * 2]     += acc[nt][2] * acc[nt][2];
                ssum[nt * 2 + 1] += acc[nt][3]; ssq[nt * 2 + 1] += acc[nt][3] * acc[nt][3];
            }
        }
    }

    // ---- flush stats: regs -> smem -> global double atomics ----
    #pragma unroll
    for (int k = 0; k < 16; k++) {
        int nt = k >> 1, j = k & 1;
        int c = (nhalf * 8 + nt) * 8 + 2 * t + j;
        atomicAdd(&sS[c], ssum[k]);
        atomicAdd(&sS[128 + c], ssq[k]);
    }
    __syncthreads();
    atomicAdd(&g_stats[layer * 256 + tid], (double)sS[tid]);
}

// ---------------- BN finalize ----------------
__global__ void k_bnstats(const float* __restrict__ gamma, const float* __restrict__ beta, int layer) {
    int c = threadIdx.x;
    double s = g_stats[layer * 256 + c];
    double q = g_stats[layer * 256 + 128 + c];
    float m = (float)(s / (double)NN);
    float v = (float)(q / (double)NN) - m * m;
    float sc = gamma[c] * rsqrtf(v + BN_EPS_F);
    g_scale[c] = sc;
    g_shift[c] = beta[c] - m * sc;
}

// ---------------- z = relu(bn(h)) ----------------
__global__ void k_bnrelu(void) {
    int i = blockIdx.x * blockDim.x + threadIdx.x;
    if (i >= NN * DD / 4) return;
    int c4 = i & 31;
    float4 hv = ((const float4*)g_h)[i];
    float4 sc = ((const float4*)g_scale)[c4];
    float4 sh = ((const float4*)g_shift)[c4];
    float4 z;
    z.x = fmaxf(fmaf(hv.x, sc.x, sh.x), 0.f);
    z.y = fmaxf(fmaf(hv.y, sc.y, sh.y), 0.f);
    z.z = fmaxf(fmaf(hv.z, sc.z, sh.z), 0.f);
    z.w = fmaxf(fmaf(hv.w, sc.w, sh.w), 0.f);
    ((float4*)g_z)[i] = z;
}

// ---------------- final: z2 = relu(bn(h2)); logits = z2@Wout; softmax ----------------
__global__ void __launch_bounds__(128) k_final(
    const float* __restrict__ Wout, const float* __restrict__ log_tau,
    float* __restrict__ out)
{
    __shared__ float sW[DD * KK];
    __shared__ float sZ[16 * DD];
    int tid = threadIdx.x;
    for (int i = tid; i < DD * KK / 4; i += 128)
        ((float4*)sW)[i] = ((const float4*)Wout)[i];

    int row0 = blockIdx.x * 16;
    for (int i = tid; i < 16 * DD / 4; i += 128) {
        int r = i >> 5;
        int c4 = i & 31;
        float4 v = make_float4(0.f, 0.f, 0.f, 0.f);
        int row = row0 + r;
        if (row < NN) {
            float4 hv = ((const float4*)(g_h + (size_t)row * DD))[c4];
            float4 sc = ((const float4*)g_scale)[c4];
            float4 sh = ((const float4*)g_shift)[c4];
            v.x = fmaxf(fmaf(hv.x, sc.x, sh.x), 0.f);
            v.y = fmaxf(fmaf(hv.y, sc.y, sh.y), 0.f);
            v.z = fmaxf(fmaf(hv.z, sc.z, sh.z), 0.f);
            v.w = fmaxf(fmaf(hv.w, sc.w, sh.w), 0.f);
        }
        ((float4*)sZ)[i] = v;
    }
    __syncthreads();

    int warp = tid >> 5, lane = tid & 31;
    float inv_tau = expf(-*log_tau);

    float acc[4][2];
    #pragma unroll
    for (int r = 0; r < 4; r++) { acc[r][0] = 0.f; acc[r][1] = 0.f; }
    #pragma unroll 4
    for (int k = 0; k < DD; k++) {
        float w0 = sW[k * KK + lane];
        float w1 = sW[k * KK + 32 + lane];
        #pragma unroll
        for (int r = 0; r < 4; r++) {
            float z = sZ[(warp * 4 + r) * DD + k];
            acc[r][0] = fmaf(z, w0, acc[r][0]);
            acc[r][1] = fmaf(z, w1, acc[r][1]);
        }
    }

    #pragma unroll
    for (int r = 0; r < 4; r++) {
        int row = row0 + warp * 4 + r;
        if (row >= NN) continue;
        float l0 = acc[r][0], l1 = acc[r][1];
        out[(size_t)NN * KK + (size_t)row * KK + lane]      = l0;
        out[(size_t)NN * KK + (size_t)row * KK + 32 + lane] = l1;
        float a0 = l0 * inv_tau, a1 = l1 * inv_tau;
        float m = fmaxf(a0, a1);
        #pragma unroll
        for (int o = 16; o > 0; o >>= 1) m = fmaxf(m, __shfl_xor_sync(0xffffffffu, m, o));
        float e0 = expf(a0 - m), e1 = expf(a1 - m);
        float s = e0 + e1;
        #pragma unroll
        for (int o = 16; o > 0; o >>= 1) s += __shfl_xor_sync(0xffffffffu, s, o);
        float inv = 1.0f / s;
        out[(size_t)row * KK + lane]      = e0 * inv;
        out[(size_t)row * KK + 32 + lane] = e1 * inv;
    }
}

// ---------------- launch ----------------
extern "C" void kernel_launch(void* const* d_in, const int* in_sizes, int n_in,
                              void* d_out, int out_size) {
    const float* x      = (const float*)d_in[0];
    const int*   ei     = (const int*)d_in[1];
    const float* W1a    = (const float*)d_in[2];
    const float* b1a    = (const float*)d_in[3];
    const float* W1b    = (const float*)d_in[4];
    const float* b1b    = (const float*)d_in[5];
    const float* eps1   = (const float*)d_in[6];
    const float* gamma1 = (const float*)d_in[7];
    const float* beta1  = (const float*)d_in[8];
    const float* W2a    = (const float*)d_in[9];
    const float* b2a    = (const float*)d_in[10];
    const float* W2b    = (const float*)d_in[11];
    const float* b2b    = (const float*)d_in[12];
    const float* eps2   = (const float*)d_in[13];
    const float* gamma2 = (const float*)d_in[14];
    const float* beta2  = (const float*)d_in[15];
    const float* Wout   = (const float*)d_in[16];
    const float* ltau   = (const float*)d_in[17];
    float* out = (float*)d_out;

    float* zptr = nullptr;
    cudaGetSymbolAddress((void**)&zptr, g_z);

    const int MLP_SMEM = 50432 * 4;   // 201728 B
    cudaFuncSetAttribute(k_mlp3, cudaFuncAttributeMaxDynamicSharedMemorySize, MLP_SMEM);

    int n_blocks   = (NN + 255) / 256;
    int e_blocks   = (EE + 255) / 256;
    int gw_blocks  = (NN * 32 + 255) / 256;
    int ew_blocks  = (NN * DD / 4 + 255) / 256;
    int fin_blocks = (NN + 15) / 16;

    // CSR build + weight prep
    k_zero<<<n_blocks, 256>>>();
    k_prepw<<<4, 256>>>(W1a, W1b, W2a, W2b);
    k_hist<<<e_blocks, 256>>>(ei);
    k_scan<<<1, 1024>>>();
    k_permute<<<e_blocks, 256>>>(ei);

    // layer 1
    k_gather<<<gw_blocks, 256>>>(x, eps1);
    k_mlp3<<<148, 256, MLP_SMEM>>>(b1a, b1b, 0);
    k_bnstats<<<1, 128>>>(gamma1, beta1, 0);
    k_bnrelu<<<ew_blocks, 256>>>();

    // layer 2
    k_gather<<<gw_blocks, 256>>>(zptr, eps2);
    k_mlp3<<<148, 256, MLP_SMEM>>>(b2a, b2b, 1);
    k_bnstats<<<1, 128>>>(gamma2, beta2, 1);
    k_final<<<fin_blocks, 128>>>(Wout, ltau, out);
}

// round 7
// speedup vs baseline: 1.4095x; 1.4095x over previous
#include <cuda_runtime.h>
#include <math.h>

#define NN 50000
#define EE 800000
#define DD 128
#define KK 64
#define BN_EPS_F 1e-5f
#define SCAN_NB 49            // ceil(50000/1024)

// ---------------- scratch (static device memory) ----------------
__device__ float  g_agg[NN * DD];
__device__ float  g_h[NN * DD];
__device__ float  g_z[NN * DD];
__device__ double g_stats[4 * DD];
__device__ float  g_scale[DD];
__device__ float  g_shift[DD];
// CSR scratch
__device__ int    g_deg[NN];
__device__ int    g_off[NN + 1];
__device__ int    g_cursor[NN];
__device__ int    g_csr[EE];
__device__ int    g_bsum[SCAN_NB];

// ---------------- zero degree + stats ----------------
__global__ void k_zero() {
    int i = blockIdx.x * blockDim.x + threadIdx.x;
    if (i < NN) g_deg[i] = 0;
    if (i < 512) g_stats[i] = 0.0;
}

// ---------------- in-degree histogram ----------------
__global__ void k_hist(const int* __restrict__ ei) {
    int e = blockIdx.x * blockDim.x + threadIdx.x;
    if (e >= EE) return;
    int d = __ldg(ei + EE + e);
    if ((unsigned)d < NN) atomicAdd(&g_deg[d], 1);
}

// ---------------- scan phase 1: per-block local exclusive scan + block total ----------------
__global__ void __launch_bounds__(1024) k_scan1() {
    __shared__ int swarp[32];
    int b = blockIdx.x, tid = threadIdx.x;
    int lane = tid & 31, w = tid >> 5;
    int i = b * 1024 + tid;
    int v = (i < NN) ? g_deg[i] : 0;
    int xv = v;
    #pragma unroll
    for (int o = 1; o < 32; o <<= 1) {
        int y = __shfl_up_sync(0xffffffffu, xv, o);
        if (lane >= o) xv += y;
    }
    if (lane == 31) swarp[w] = xv;
    __syncthreads();
    if (w == 0) {
        int y = swarp[lane];
        #pragma unroll
        for (int o = 1; o < 32; o <<= 1) {
            int z = __shfl_up_sync(0xffffffffu, y, o);
            if (lane >= o) y += z;
        }
        swarp[lane] = y;
    }
    __syncthreads();
    int excl = xv - v + (w > 0 ? swarp[w - 1] : 0);
    if (i < NN) g_off[i] = excl;
    if (tid == 1023) g_bsum[b] = excl + v;
}

// ---------------- scan phase 2: add block prefix, init cursors ----------------
__global__ void __launch_bounds__(1024) k_scan2() {
    __shared__ int partial[2];
    int b = blockIdx.x, tid = threadIdx.x;
    int v = 0;
    if (tid < 64) {
        if (tid < SCAN_NB && tid < b) v = g_bsum[tid];
        #pragma unroll
        for (int o = 16; o > 0; o >>= 1) v += __shfl_down_sync(0xffffffffu, v, o);
        if ((tid & 31) == 0) partial[tid >> 5] = v;
    }
    __syncthreads();
    int base = partial[0] + partial[1];
    int i = b * 1024 + tid;
    if (i < NN) {
        int o = g_off[i] + base;
        g_off[i] = o;
        g_cursor[i] = o;
    }
    if (b == SCAN_NB - 1 && tid == 0) g_off[NN] = base + g_bsum[b];
}

// ---------------- permute: fill CSR src lists ----------------
__global__ void k_permute(const int* __restrict__ ei) {
    int e = blockIdx.x * blockDim.x + threadIdx.x;
    if (e >= EE) return;
    int s = __ldg(ei + e);
    int d = __ldg(ei + EE + e);
    if ((unsigned)s >= NN || (unsigned)d >= NN) return;
    int pos = atomicAdd(&g_cursor[d], 1);
    g_csr[pos] = s;
}

// ---------------- gather: agg[n] = (1+eps)*feat[n] + sum_{s in N(n)} feat[s] ----------------
__global__ void k_gather(const float* __restrict__ feat, const float* __restrict__ epsp) {
    int gw = (blockIdx.x * blockDim.x + threadIdx.x) >> 5;
    int lane = threadIdx.x & 31;
    if (gw >= NN) return;
    float e = 1.0f + *epsp;
    float4 acc = __ldg((const float4*)(feat + (size_t)gw * DD) + lane);
    acc.x *= e; acc.y *= e; acc.z *= e; acc.w *= e;
    int beg = __ldg(&g_off[gw]);
    int end = __ldg(&g_off[gw + 1]);
    int j = beg;
    for (; j + 4 <= end; j += 4) {
        int s0 = __ldg(&g_csr[j]);
        int s1 = __ldg(&g_csr[j + 1]);
        int s2 = __ldg(&g_csr[j + 2]);
        int s3 = __ldg(&g_csr[j + 3]);
        float4 v0 = __ldg((const float4*)(feat + (size_t)s0 * DD) + lane);
        float4 v1 = __ldg((const float4*)(feat + (size_t)s1 * DD) + lane);
        float4 v2 = __ldg((const float4*)(feat + (size_t)s2 * DD) + lane);
        float4 v3 = __ldg((const float4*)(feat + (size_t)s3 * DD) + lane);
        acc.x += (v0.x + v1.x) + (v2.x + v3.x);
        acc.y += (v0.y + v1.y) + (v2.y + v3.y);
        acc.z += (v0.z + v1.z) + (v2.z + v3.z);
        acc.w += (v0.w + v1.w) + (v2.w + v3.w);
    }
    for (; j < end; j++) {
        int s = __ldg(&g_csr[j]);
        float4 v = __ldg((const float4*)(feat + (size_t)s * DD) + lane);
        acc.x += v.x; acc.y += v.y; acc.z += v.z; acc.w += v.w;
    }
    ((float4*)(g_agg + (size_t)gw * DD))[lane] = acc;
}

// ---------------- fused 2-GEMM MLP (fp32 FFMA) + BN stats ----------------
__global__ void __launch_bounds__(256, 1) k_mlp(
    const float* __restrict__ Wa, const float* __restrict__ ba,
    const float* __restrict__ Wb, const float* __restrict__ bb, int layer)
{
    extern __shared__ float sm[];
    float* sWa = sm;
    float* sWb = sm + 16384;
    float* sA  = sm + 32768;
    float* sT  = sm + 40960;
    float* sS  = sm + 49152;

    int tid = threadIdx.x;
    for (int i = tid; i < 4096; i += 256) {
        ((float4*)sWa)[i] = ((const float4*)Wa)[i];
        ((float4*)sWb)[i] = ((const float4*)Wb)[i];
    }
    sS[tid] = 0.0f;

    int tx = tid & 31;
    int ty = tid >> 5;
    float4 ba4 = *(const float4*)(ba + tx * 4);
    float4 bb4 = *(const float4*)(bb + tx * 4);
    __syncthreads();

    const int ntiles = (NN + 63) / 64;
    for (int t = blockIdx.x; t < ntiles; t += gridDim.x) {
        int row0 = t * 64;
        int rows = NN - row0; if (rows > 64) rows = 64;

        for (int i = tid; i < 2048; i += 256) {
            int r = i >> 5;
            float4 v = make_float4(0.f, 0.f, 0.f, 0.f);
            if (r < rows) v = ((const float4*)(g_agg + (size_t)(row0 + r) * DD))[i & 31];
            ((float4*)sA)[i] = v;
        }
        __syncthreads();

        float acc[8][4];
        #pragma unroll
        for (int r = 0; r < 8; r++) { acc[r][0] = ba4.x; acc[r][1] = ba4.y; acc[r][2] = ba4.z; acc[r][3] = ba4.w; }
        #pragma unroll 8
        for (int k = 0; k < DD; k++) {
            float4 w = ((const float4*)(sWa + k * DD))[tx];
            #pragma unroll
            for (int r = 0; r < 8; r++) {
                float a = sA[(ty * 8 + r) * DD + k];
                acc[r][0] = fmaf(a, w.x, acc[r][0]);
                acc[r][1] = fmaf(a, w.y, acc[r][1]);
                acc[r][2] = fmaf(a, w.z, acc[r][2]);
                acc[r][3] = fmaf(a, w.w, acc[r][3]);
            }
        }
        #pragma unroll
        for (int r = 0; r < 8; r++) {
            float4 v = make_float4(fmaxf(acc[r][0], 0.f), fmaxf(acc[r][1], 0.f),
                                   fmaxf(acc[r][2], 0.f), fmaxf(acc[r][3], 0.f));
            ((float4*)(sT + (ty * 8 + r) * DD))[tx] = v;
        }
        __syncthreads();

        #pragma unroll
        for (int r = 0; r < 8; r++) { acc[r][0] = bb4.x; acc[r][1] = bb4.y; acc[r][2] = bb4.z; acc[r][3] = bb4.w; }
        #pragma unroll 8
        for (int k = 0; k < DD; k++) {
            float4 w = ((const float4*)(sWb + k * DD))[tx];
            #pragma unroll
            for (int r = 0; r < 8; r++) {
                float a = sT[(ty * 8 + r) * DD + k];
                acc[r][0] = fmaf(a, w.x, acc[r][0]);
                acc[r][1] = fmaf(a, w.y, acc[r][1]);
                acc[r][2] = fmaf(a, w.z, acc[r][2]);
                acc[r][3] = fmaf(a, w.w, acc[r][3]);
            }
        }

        float s0 = 0.f, s1 = 0.f, s2 = 0.f, s3 = 0.f;
        float q0 = 0.f, q1 = 0.f, q2 = 0.f, q3 = 0.f;
        #pragma unroll
        for (int r = 0; r < 8; r++) {
            int rr = ty * 8 + r;
            if (rr < rows) {
                float4 v = make_float4(acc[r][0], acc[r][1], acc[r][2], acc[r][3]);
                ((float4*)(g_h + (size_t)(row0 + rr) * DD))[tx] = v;
                s0 += v.x; q0 += v.x * v.x;
                s1 += v.y; q1 += v.y * v.y;
                s2 += v.z; q2 += v.z * v.z;
                s3 += v.w; q3 += v.w * v.w;
            }
        }
        int c = tx * 4;
        atomicAdd(&sS[c + 0], s0); atomicAdd(&sS[128 + c + 0], q0);
        atomicAdd(&sS[c + 1], s1); atomicAdd(&sS[128 + c + 1], q1);
        atomicAdd(&sS[c + 2], s2); atomicAdd(&sS[128 + c + 2], q2);
        atomicAdd(&sS[c + 3], s3); atomicAdd(&sS[128 + c + 3], q3);
        __syncthreads();
    }
    atomicAdd(&g_stats[layer * 256 + tid], (double)sS[tid]);
}

// ---------------- BN finalize ----------------
__global__ void k_bnstats(const float* __restrict__ gamma, const float* __restrict__ beta, int layer) {
    int c = threadIdx.x;
    double s = g_stats[layer * 256 + c];
    double q = g_stats[layer * 256 + 128 + c];
    float m = (float)(s / (double)NN);
    float v = (float)(q / (double)NN) - m * m;
    float sc = gamma[c] * rsqrtf(v + BN_EPS_F);
    g_scale[c] = sc;
    g_shift[c] = beta[c] - m * sc;
}

// ---------------- z = relu(bn(h)) ----------------
__global__ void k_bnrelu(void) {
    int i = blockIdx.x * blockDim.x + threadIdx.x;
    if (i >= NN * DD / 4) return;
    int c4 = i & 31;
    float4 hv = ((const float4*)g_h)[i];
    float4 sc = ((const float4*)g_scale)[c4];
    float4 sh = ((const float4*)g_shift)[c4];
    float4 z;
    z.x = fmaxf(fmaf(hv.x, sc.x, sh.x), 0.f);
    z.y = fmaxf(fmaf(hv.y, sc.y, sh.y), 0.f);
    z.z = fmaxf(fmaf(hv.z, sc.z, sh.z), 0.f);
    z.w = fmaxf(fmaf(hv.w, sc.w, sh.w), 0.f);
    ((float4*)g_z)[i] = z;
}

// ---------------- final: z2 = relu(bn(h2)); logits = z2@Wout; softmax ----------------
__global__ void __launch_bounds__(128) k_final(
    const float* __restrict__ Wout, const float* __restrict__ log_tau,
    float* __restrict__ out)
{
    __shared__ float sW[DD * KK];
    __shared__ float sZ[16 * DD];
    int tid = threadIdx.x;
    for (int i = tid; i < DD * KK / 4; i += 128)
        ((float4*)sW)[i] = ((const float4*)Wout)[i];

    int row0 = blockIdx.x * 16;
    for (int i = tid; i < 16 * DD / 4; i += 128) {
        int r = i >> 5;
        int c4 = i & 31;
        float4 v = make_float4(0.f, 0.f, 0.f, 0.f);
        int row = row0 + r;
        if (row < NN) {
            float4 hv = ((const float4*)(g_h + (size_t)row * DD))[c4];
            float4 sc = ((const float4*)g_scale)[c4];
            float4 sh = ((const float4*)g_shift)[c4];
            v.x = fmaxf(fmaf(hv.x, sc.x, sh.x), 0.f);
            v.y = fmaxf(fmaf(hv.y, sc.y, sh.y), 0.f);
            v.z = fmaxf(fmaf(hv.z, sc.z, sh.z), 0.f);
            v.w = fmaxf(fmaf(hv.w, sc.w, sh.w), 0.f);
        }
        ((float4*)sZ)[i] = v;
    }
    __syncthreads();

    int warp = tid >> 5, lane = tid & 31;
    float inv_tau = expf(-*log_tau);

    float acc[4][2];
    #pragma unroll
    for (int r = 0; r < 4; r++) { acc[r][0] = 0.f; acc[r][1] = 0.f; }
    #pragma unroll 4
    for (int k = 0; k < DD; k++) {
        float w0 = sW[k * KK + lane];
        float w1 = sW[k * KK + 32 + lane];
        #pragma unroll
        for (int r = 0; r < 4; r++) {
            float z = sZ[(warp * 4 + r) * DD + k];
            acc[r][0] = fmaf(z, w0, acc[r][0]);
            acc[r][1] = fmaf(z, w1, acc[r][1]);
        }
    }

    #pragma unroll
    for (int r = 0; r < 4; r++) {
        int row = row0 + warp * 4 + r;
        if (row >= NN) continue;
        float l0 = acc[r][0], l1 = acc[r][1];
        out[(size_t)NN * KK + (size_t)row * KK + lane]      = l0;
        out[(size_t)NN * KK + (size_t)row * KK + 32 + lane] = l1;
        float a0 = l0 * inv_tau, a1 = l1 * inv_tau;
        float m = fmaxf(a0, a1);
        #pragma unroll
        for (int o = 16; o > 0; o >>= 1) m = fmaxf(m, __shfl_xor_sync(0xffffffffu, m, o));
        float e0 = expf(a0 - m), e1 = expf(a1 - m);
        float s = e0 + e1;
        #pragma unroll
        for (int o = 16; o > 0; o >>= 1) s += __shfl_xor_sync(0xffffffffu, s, o);
        float inv = 1.0f / s;
        out[(size_t)row * KK + lane]      = e0 * inv;
        out[(size_t)row * KK + 32 + lane] = e1 * inv;
    }
}

// ---------------- launch ----------------
extern "C" void kernel_launch(void* const* d_in, const int* in_sizes, int n_in,
                              void* d_out, int out_size) {
    const float* x      = (const float*)d_in[0];
    const int*   ei     = (const int*)d_in[1];
    const float* W1a    = (const float*)d_in[2];
    const float* b1a    = (const float*)d_in[3];
    const float* W1b    = (const float*)d_in[4];
    const float* b1b    = (const float*)d_in[5];
    const float* eps1   = (const float*)d_in[6];
    const float* gamma1 = (const float*)d_in[7];
    const float* beta1  = (const float*)d_in[8];
    const float* W2a    = (const float*)d_in[9];
    const float* b2a    = (const float*)d_in[10];
    const float* W2b    = (const float*)d_in[11];
    const float* b2b    = (const float*)d_in[12];
    const float* eps2   = (const float*)d_in[13];
    const float* gamma2 = (const float*)d_in[14];
    const float* beta2  = (const float*)d_in[15];
    const float* Wout   = (const float*)d_in[16];
    const float* ltau   = (const float*)d_in[17];
    float* out = (float*)d_out;

    float* zptr = nullptr;
    cudaGetSymbolAddress((void**)&zptr, g_z);

    const int MLP_SMEM = 49408 * 4;   // 197632 B
    cudaFuncSetAttribute(k_mlp, cudaFuncAttributeMaxDynamicSharedMemorySize, MLP_SMEM);

    int n_blocks   = (NN + 255) / 256;
    int e_blocks   = (EE + 255) / 256;
    int gw_blocks  = (NN * 32 + 255) / 256;
    int ew_blocks  = (NN * DD / 4 + 255) / 256;
    int fin_blocks = (NN + 15) / 16;

    // CSR build (multi-block scan)
    k_zero<<<n_blocks, 256>>>();
    k_hist<<<e_blocks, 256>>>(ei);
    k_scan1<<<SCAN_NB, 1024>>>();
    k_scan2<<<SCAN_NB, 1024>>>();
    k_permute<<<e_blocks, 256>>>(ei);

    // layer 1
    k_gather<<<gw_blocks, 256>>>(x, eps1);
    k_mlp<<<148, 256, MLP_SMEM>>>(W1a, b1a, W1b, b1b, 0);
    k_bnstats<<<1, 128>>>(gamma1, beta1, 0);
    k_bnrelu<<<ew_blocks, 256>>>();

    // layer 2
    k_gather<<<gw_blocks, 256>>>(zptr, eps2);
    k_mlp<<<148, 256, MLP_SMEM>>>(W2a, b2a, W2b, b2b, 1);
    k_bnstats<<<1, 128>>>(gamma2, beta2, 1);
    k_final<<<fin_blocks, 128>>>(Wout, ltau, out);
}